// round 13
// baseline (speedup 1.0000x reference)
#include <cuda_runtime.h>
#include <stdint.h>
#include <math.h>

#define NNODES 100000
#define NEDGES 1000000
#define FDIM   128
#define F2DIM  188
#define NCLS   47
#define NHEAD  4
#define BN_EPS 1e-5f

// ---------------- scratch (device globals; no allocation allowed) ----------------
__device__ float g_fs[(size_t)NNODES * F2DIM];
__device__ float g_fd[(size_t)NNODES * F2DIM];
__device__ float g_res[(size_t)NNODES * F2DIM];
__device__ float g_hA[(size_t)NNODES * FDIM];
__device__ float g_hB[(size_t)NNODES * FDIM];
__device__ int   g_rowptr[NNODES + 1];
__device__ float g_bnsum0[FDIM];
__device__ float g_bnsq0[FDIM];
__device__ float g_bnsum1[FDIM];
__device__ float g_bnsq1[FDIM];

// ---------------- CSR row_ptr from sorted dst (+ zero BN accumulators) ----------------
__global__ void build_rowptr(const int* __restrict__ dst, int E, int N) {
    int e = blockIdx.x * blockDim.x + threadIdx.x;
    if (blockIdx.x == 0 && threadIdx.x < FDIM) {
        g_bnsum0[threadIdx.x] = 0.f; g_bnsq0[threadIdx.x] = 0.f;
        g_bnsum1[threadIdx.x] = 0.f; g_bnsq1[threadIdx.x] = 0.f;
    }
    if (e >= E) return;
    int d = dst[e];
    int dprev = (e == 0) ? -1 : dst[e - 1];
    for (int n = dprev + 1; n <= d; n++) g_rowptr[n] = e;
    if (e == E - 1) {
        for (int n = d + 1; n <= N; n++) g_rowptr[n] = E;
    }
}

// ---------------- cp.async helpers ----------------
__device__ __forceinline__ void cp_async16(uint32_t smem_addr, const void* gptr, int src_bytes) {
    asm volatile("cp.async.cg.shared.global [%0], [%1], 16, %2;\n"
                 :: "r"(smem_addr), "l"(gptr), "r"(src_bytes));
}
__device__ __forceinline__ void cp_commit() {
    asm volatile("cp.async.commit_group;\n");
}
template <int NN>
__device__ __forceinline__ void cp_wait() {
    asm volatile("cp.async.wait_group %0;\n" :: "n"(NN));
}

// ---------------- split-tf32 tensor-core GEMM, cp.async double-buffered ----------------
// R10-proven 2-stage pipeline structure; BK widened 16 -> 32 (half the barrier events).
// Tile: block 128x64, 256 threads (8 warps, warp tile 32x32).
// blockIdx.z selects among up to 3 weight matrices sharing the same A.

#define BM 128
#define BNT 64
#define BKT 32
#define APAD 36    // A row stride (floats): (36g + t4) mod 32 covers all banks
#define BSTR 72    // B row stride: (8*t4 + g) mod 32 covers all banks

__device__ __forceinline__ float tf32_rna(float x) {
    float r;
    asm("cvt.rna.tf32.f32 %0, %1;" : "=f"(r) : "f"(x));
    return r;
}

__device__ __forceinline__ void mma_tf32(float* d, const float* a, const float* b) {
    asm volatile(
        "mma.sync.aligned.m16n8k8.row.col.f32.tf32.tf32.f32 "
        "{%0,%1,%2,%3}, {%4,%5,%6,%7}, {%8,%9}, {%0,%1,%2,%3};"
        : "+f"(d[0]), "+f"(d[1]), "+f"(d[2]), "+f"(d[3])
        : "r"(__float_as_uint(a[0])), "r"(__float_as_uint(a[1])),
          "r"(__float_as_uint(a[2])), "r"(__float_as_uint(a[3])),
          "r"(__float_as_uint(b[0])), "r"(__float_as_uint(b[1])));
}

__global__ __launch_bounds__(256, 2)
void gemm3_tf32(const float* __restrict__ A,
                const float* __restrict__ W0, const float* __restrict__ W1, const float* __restrict__ W2,
                const float* __restrict__ b0, const float* __restrict__ b1, const float* __restrict__ b2,
                float* __restrict__ C0, float* __restrict__ C1, float* __restrict__ C2,
                int nrows, int K, int ncols) {
    __shared__ float As[2][BM][APAD];
    __shared__ float Bs[2][BKT][BSTR];

    int z = blockIdx.z;
    const float* W    = (z == 0) ? W0 : ((z == 1) ? W1 : W2);
    const float* bias = (z == 0) ? b0 : ((z == 1) ? b1 : b2);
    float* C          = (z == 0) ? C0 : ((z == 1) ? C1 : C2);

    int tid = threadIdx.x;
    int warp = tid >> 5, lane = tid & 31;
    int wm = warp & 3;
    int wn = warp >> 2;
    int g = lane >> 2, t4 = lane & 3;
    int row0 = blockIdx.x * BM;
    int col0 = blockIdx.y * BNT;

    // loader mapping (BK=32)
    int a_row = tid >> 1;              // 0..127
    int a_kc  = (tid & 1) * 16;        // 0 or 16: four 16B chunks at +0,+4,+8,+12
    int b_kr  = tid >> 3;              // 0..31
    int b_nc  = (tid & 7) * 8;         // 0..56: two 16B chunks at +0,+4

    int arow_g = row0 + a_row;
    bool arow_ok = arow_g < nrows;
    const float* Arow = A + (size_t)(arow_ok ? arow_g : 0) * K;

    float acc[2][4][4];
#pragma unroll
    for (int mt = 0; mt < 2; mt++)
#pragma unroll
        for (int nt = 0; nt < 4; nt++)
#pragma unroll
            for (int r = 0; r < 4; r++) acc[mt][nt][r] = 0.f;

    int niter = (K + BKT - 1) / BKT;

    uint32_t sA0 = (uint32_t)__cvta_generic_to_shared(&As[0][a_row][a_kc]);
    uint32_t sA1 = (uint32_t)__cvta_generic_to_shared(&As[1][a_row][a_kc]);
    uint32_t sB0 = (uint32_t)__cvta_generic_to_shared(&Bs[0][b_kr][b_nc]);
    uint32_t sB1 = (uint32_t)__cvta_generic_to_shared(&Bs[1][b_kr][b_nc]);

    auto prefetch = [&](int stage, int k0) {
        uint32_t sA = stage ? sA1 : sA0;
        uint32_t sB = stage ? sB1 : sB0;
#pragma unroll
        for (int q = 0; q < 4; q++) {
            int kk = k0 + a_kc + 4 * q;
            int bytes = (arow_ok && (kk + 4 <= K)) ? 16 : 0;   // K multiple of 4; zero-fill padding
            cp_async16(sA + 16 * q, Arow + (bytes ? kk : 0), bytes);
        }
#pragma unroll
        for (int q = 0; q < 2; q++) {
            int kk = k0 + b_kr;
            int cc = col0 + b_nc + 4 * q;
            int bytes = (kk < K && (cc + 4 <= ncols)) ? 16 : 0;
            const float* src = W + (size_t)(bytes ? kk : 0) * ncols + (bytes ? cc : 0);
            cp_async16(sB + 16 * q, src, bytes);
        }
    };

    prefetch(0, 0);
    cp_commit();

    int buf = 0;
    for (int it = 0; it < niter; it++) {
        if (it + 1 < niter) prefetch(buf ^ 1, (it + 1) * BKT);
        cp_commit();
        cp_wait<1>();
        __syncthreads();

        // ---- compute stage buf: 4 k-steps of m16n8k8 ----
#pragma unroll
        for (int ks = 0; ks < 4; ks++) {
            int kb = ks * 8;
            float ah[2][4], al[2][4];
#pragma unroll
            for (int mt = 0; mt < 2; mt++) {
                int mr = wm * 32 + mt * 16 + g;
                float r0 = As[buf][mr][kb + t4];
                float r1 = As[buf][mr + 8][kb + t4];
                float r2 = As[buf][mr][kb + t4 + 4];
                float r3 = As[buf][mr + 8][kb + t4 + 4];
                ah[mt][0] = tf32_rna(r0); al[mt][0] = tf32_rna(r0 - ah[mt][0]);
                ah[mt][1] = tf32_rna(r1); al[mt][1] = tf32_rna(r1 - ah[mt][1]);
                ah[mt][2] = tf32_rna(r2); al[mt][2] = tf32_rna(r2 - ah[mt][2]);
                ah[mt][3] = tf32_rna(r3); al[mt][3] = tf32_rna(r3 - ah[mt][3]);
            }
            float bh[4][2], bl[4][2];
#pragma unroll
            for (int nt = 0; nt < 4; nt++) {
                int nc = wn * 32 + nt * 8 + g;
                float r0 = Bs[buf][kb + t4][nc];
                float r1 = Bs[buf][kb + t4 + 4][nc];
                bh[nt][0] = tf32_rna(r0); bl[nt][0] = tf32_rna(r0 - bh[nt][0]);
                bh[nt][1] = tf32_rna(r1); bl[nt][1] = tf32_rna(r1 - bh[nt][1]);
            }
#pragma unroll
            for (int mt = 0; mt < 2; mt++)
#pragma unroll
                for (int nt = 0; nt < 4; nt++) {
                    mma_tf32(acc[mt][nt], ah[mt], bh[nt]);
                    mma_tf32(acc[mt][nt], ah[mt], bl[nt]);
                    mma_tf32(acc[mt][nt], al[mt], bh[nt]);
                }
        }
        __syncthreads();
        buf ^= 1;
    }

    // ---- epilogue: bias add + store ----
#pragma unroll
    for (int mt = 0; mt < 2; mt++) {
#pragma unroll
        for (int nt = 0; nt < 4; nt++) {
            int row = row0 + wm * 32 + mt * 16 + g;
            int col = col0 + wn * 32 + nt * 8 + 2 * t4;
            if (col < ncols) {
                float b0v = bias[col], b1v = bias[col + 1];
                if (row < nrows) {
                    float2 v = make_float2(acc[mt][nt][0] + b0v, acc[mt][nt][1] + b1v);
                    *reinterpret_cast<float2*>(C + (size_t)row * ncols + col) = v;
                }
                if (row + 8 < nrows) {
                    float2 v = make_float2(acc[mt][nt][2] + b0v, acc[mt][nt][3] + b1v);
                    *reinterpret_cast<float2*>(C + (size_t)(row + 8) * ncols + col) = v;
                }
            }
        }
    }
}

// ---------------- GATv2 aggregation, F=128 (H=4, D=32), fused BN-stats ----------------
// Warp per node; lane owns a float4 chunk. 2-edge unroll.
// REQUIRES: grid*8 == N exactly (all warps live through __syncthreads).
__global__ void gat_agg128(const float* __restrict__ fs, const float* __restrict__ fd,
                           const float* __restrict__ attn, const float* __restrict__ res,
                           float* __restrict__ out, const int* __restrict__ srcidx,
                           float* __restrict__ bsum, float* __restrict__ bsq, int N) {
    __shared__ float sred[8][256];   // per-warp: [0..127]=val, [128..255]=val^2

    int wid  = threadIdx.x >> 5;
    int lane = threadIdx.x & 31;
    int n = blockIdx.x * 8 + wid;    // n < N by construction

    const float4* fs4   = (const float4*)fs;
    const float4* fd4   = (const float4*)fd;
    const float4* attn4 = (const float4*)attn;
    const float4* res4  = (const float4*)res;
    float4* out4 = (float4*)out;

    float4 fdv = fd4[(size_t)n * 32 + lane];
    float4 av  = attn4[lane];
    float4 acc = make_float4(0.f, 0.f, 0.f, 0.f);
    float m = -1e30f, s = 0.f;

    int e0 = g_rowptr[n], e1 = g_rowptr[n + 1];
    float4 f0 = make_float4(0.f, 0.f, 0.f, 0.f);
    float4 f1 = f0;
    if (e0 < e1)     f0 = __ldg(&fs4[(size_t)__ldg(&srcidx[e0]) * 32 + lane]);
    if (e0 + 1 < e1) f1 = __ldg(&fs4[(size_t)__ldg(&srcidx[e0 + 1]) * 32 + lane]);

    for (int e = e0; e < e1; e += 2) {
        float4 c0 = f0, c1 = f1;
        bool v1 = (e + 1) < e1;
        if (e + 2 < e1) f0 = __ldg(&fs4[(size_t)__ldg(&srcidx[e + 2]) * 32 + lane]);
        if (e + 3 < e1) f1 = __ldg(&fs4[(size_t)__ldg(&srcidx[e + 3]) * 32 + lane]);

        float ax, ay, az, aw;
        ax = c0.x + fdv.x; ax = (ax > 0.f) ? ax : 0.2f * ax;
        ay = c0.y + fdv.y; ay = (ay > 0.f) ? ay : 0.2f * ay;
        az = c0.z + fdv.z; az = (az > 0.f) ? az : 0.2f * az;
        aw = c0.w + fdv.w; aw = (aw > 0.f) ? aw : 0.2f * aw;
        float t0 = ax * av.x + ay * av.y + az * av.z + aw * av.w;

        ax = c1.x + fdv.x; ax = (ax > 0.f) ? ax : 0.2f * ax;
        ay = c1.y + fdv.y; ay = (ay > 0.f) ? ay : 0.2f * ay;
        az = c1.z + fdv.z; az = (az > 0.f) ? az : 0.2f * az;
        aw = c1.w + fdv.w; aw = (aw > 0.f) ? aw : 0.2f * aw;
        float t1 = ax * av.x + ay * av.y + az * av.z + aw * av.w;

        t0 += __shfl_xor_sync(0xffffffffu, t0, 4);
        t1 += __shfl_xor_sync(0xffffffffu, t1, 4);
        t0 += __shfl_xor_sync(0xffffffffu, t0, 2);
        t1 += __shfl_xor_sync(0xffffffffu, t1, 2);
        t0 += __shfl_xor_sync(0xffffffffu, t0, 1);
        t1 += __shfl_xor_sync(0xffffffffu, t1, 1);

        if (t0 > m) {
            float c = __expf(m - t0);
            acc.x *= c; acc.y *= c; acc.z *= c; acc.w *= c;
            s *= c; m = t0;
        }
        float p0 = __expf(t0 - m);
        s += p0;
        acc.x = fmaf(p0, c0.x, acc.x);
        acc.y = fmaf(p0, c0.y, acc.y);
        acc.z = fmaf(p0, c0.z, acc.z);
        acc.w = fmaf(p0, c0.w, acc.w);

        if (v1) {
            if (t1 > m) {
                float c = __expf(m - t1);
                acc.x *= c; acc.y *= c; acc.z *= c; acc.w *= c;
                s *= c; m = t1;
            }
            float p1 = __expf(t1 - m);
            s += p1;
            acc.x = fmaf(p1, c1.x, acc.x);
            acc.y = fmaf(p1, c1.y, acc.y);
            acc.z = fmaf(p1, c1.z, acc.z);
            acc.w = fmaf(p1, c1.w, acc.w);
        }
    }
    float inv = (e1 > e0) ? (1.f / s) : 0.f;
    float4 r = res4[(size_t)n * 32 + lane];
    float4 o;
    o.x = fmaxf(fmaf(acc.x, inv, r.x), 0.f);
    o.y = fmaxf(fmaf(acc.y, inv, r.y), 0.f);
    o.z = fmaxf(fmaf(acc.z, inv, r.z), 0.f);
    o.w = fmaxf(fmaf(acc.w, inv, r.w), 0.f);
    out4[(size_t)n * 32 + lane] = o;

    // ---- fused BN statistics ----
    int c4 = lane * 4;
    sred[wid][c4 + 0] = o.x;  sred[wid][128 + c4 + 0] = o.x * o.x;
    sred[wid][c4 + 1] = o.y;  sred[wid][128 + c4 + 1] = o.y * o.y;
    sred[wid][c4 + 2] = o.z;  sred[wid][128 + c4 + 2] = o.z * o.z;
    sred[wid][c4 + 3] = o.w;  sred[wid][128 + c4 + 3] = o.w * o.w;
    __syncthreads();
    int t = threadIdx.x;
    if (t < 128) {
        float ss = 0.f, qq = 0.f;
#pragma unroll
        for (int w = 0; w < 8; w++) {
            ss += sred[w][t];
            qq += sred[w][128 + t];
        }
        atomicAdd(&bsum[t], ss);
        atomicAdd(&bsq[t], qq);
    }
}

// ---------------- Layer-2 aggregation (C=47) + head-mean + log_softmax ----------------
__global__ void gat_agg_final(const float* __restrict__ fs, const float* __restrict__ fd,
                              const float* __restrict__ attn, const float* __restrict__ res,
                              float* __restrict__ out, const int* __restrict__ srcidx, int N) {
    int warp = (blockIdx.x * blockDim.x + threadIdx.x) >> 5;
    int lane = threadIdx.x & 31;
    if (warp >= N) return;
    int n = warp;
    int h = lane >> 3, sub = lane & 7;
    int c0i = sub * 6;
    int cnt = (47 - c0i < 6) ? (47 - c0i) : 6;   // 6 or 5
    int base = h * 47 + c0i;

    float fdv[6], av[6], acc[6];
#pragma unroll
    for (int j = 0; j < 6; j++) {
        bool valid = j < cnt;
        fdv[j] = valid ? fd[(size_t)n * 188 + base + j] : 0.f;
        av[j]  = valid ? attn[base + j] : 0.f;
        acc[j] = 0.f;
    }
    float m = -1e30f, s = 0.f;

    int e0 = g_rowptr[n], e1 = g_rowptr[n + 1];
    float f0[6], f1[6];
#pragma unroll
    for (int j = 0; j < 6; j++) { f0[j] = 0.f; f1[j] = 0.f; }
    if (e0 < e1) {
        const float* p = fs + (size_t)__ldg(&srcidx[e0]) * 188 + base;
#pragma unroll
        for (int j = 0; j < 6; j++) if (j < cnt) f0[j] = __ldg(&p[j]);
    }
    if (e0 + 1 < e1) {
        const float* p = fs + (size_t)__ldg(&srcidx[e0 + 1]) * 188 + base;
#pragma unroll
        for (int j = 0; j < 6; j++) if (j < cnt) f1[j] = __ldg(&p[j]);
    }

    for (int e = e0; e < e1; e += 2) {
        float c0[6], c1[6];
#pragma unroll
        for (int j = 0; j < 6; j++) { c0[j] = f0[j]; c1[j] = f1[j]; }
        bool v1 = (e + 1) < e1;
        if (e + 2 < e1) {
            const float* p = fs + (size_t)__ldg(&srcidx[e + 2]) * 188 + base;
#pragma unroll
            for (int j = 0; j < 6; j++) if (j < cnt) f0[j] = __ldg(&p[j]);
        }
        if (e + 3 < e1) {
            const float* p = fs + (size_t)__ldg(&srcidx[e + 3]) * 188 + base;
#pragma unroll
            for (int j = 0; j < 6; j++) if (j < cnt) f1[j] = __ldg(&p[j]);
        }

        float t0 = 0.f, t1 = 0.f;
#pragma unroll
        for (int j = 0; j < 6; j++) {
            float v = c0[j] + fdv[j];
            v = (v > 0.f) ? v : 0.2f * v;
            t0 = fmaf(v, av[j], t0);
        }
#pragma unroll
        for (int j = 0; j < 6; j++) {
            float v = c1[j] + fdv[j];
            v = (v > 0.f) ? v : 0.2f * v;
            t1 = fmaf(v, av[j], t1);
        }
        t0 += __shfl_xor_sync(0xffffffffu, t0, 4);
        t1 += __shfl_xor_sync(0xffffffffu, t1, 4);
        t0 += __shfl_xor_sync(0xffffffffu, t0, 2);
        t1 += __shfl_xor_sync(0xffffffffu, t1, 2);
        t0 += __shfl_xor_sync(0xffffffffu, t0, 1);
        t1 += __shfl_xor_sync(0xffffffffu, t1, 1);

        if (t0 > m) {
            float c = __expf(m - t0);
#pragma unroll
            for (int j = 0; j < 6; j++) acc[j] *= c;
            s *= c; m = t0;
        }
        float p0 = __expf(t0 - m);
        s += p0;
#pragma unroll
        for (int j = 0; j < 6; j++) acc[j] = fmaf(p0, c0[j], acc[j]);

        if (v1) {
            if (t1 > m) {
                float c = __expf(m - t1);
#pragma unroll
                for (int j = 0; j < 6; j++) acc[j] *= c;
                s *= c; m = t1;
            }
            float p1 = __expf(t1 - m);
            s += p1;
#pragma unroll
            for (int j = 0; j < 6; j++) acc[j] = fmaf(p1, c1[j], acc[j]);
        }
    }

    float inv = (e1 > e0) ? (1.f / s) : 0.f;
    float v[6];
#pragma unroll
    for (int j = 0; j < 6; j++) {
        float rr = (j < cnt) ? res[(size_t)n * 188 + base + j] : 0.f;
        v[j] = fmaf(acc[j], inv, rr);
    }
#pragma unroll
    for (int j = 0; j < 6; j++) {
        v[j] += __shfl_xor_sync(0xffffffffu, v[j], 8);
        v[j] += __shfl_xor_sync(0xffffffffu, v[j], 16);
        v[j] *= 0.25f;
    }
    float lm = -1e30f;
#pragma unroll
    for (int j = 0; j < 6; j++) if (j < cnt) lm = fmaxf(lm, v[j]);
    lm = fmaxf(lm, __shfl_xor_sync(0xffffffffu, lm, 4));
    lm = fmaxf(lm, __shfl_xor_sync(0xffffffffu, lm, 2));
    lm = fmaxf(lm, __shfl_xor_sync(0xffffffffu, lm, 1));
    float ls = 0.f;
#pragma unroll
    for (int j = 0; j < 6; j++) if (j < cnt) ls += __expf(v[j] - lm);
    ls += __shfl_xor_sync(0xffffffffu, ls, 4);
    ls += __shfl_xor_sync(0xffffffffu, ls, 2);
    ls += __shfl_xor_sync(0xffffffffu, ls, 1);
    float lse = lm + logf(ls);
    if (h == 0) {
#pragma unroll
        for (int j = 0; j < 6; j++)
            if (j < cnt) out[(size_t)n * 47 + c0i + j] = v[j] - lse;
    }
}

// ---------------- BatchNorm apply: smem-precomputed scale/shift, relu fused ----------------
__global__ void bn_apply(const float4* __restrict__ X, float4* __restrict__ Y,
                         const float* __restrict__ g, const float* __restrict__ b,
                         const float* __restrict__ bsum, const float* __restrict__ bsq, int nrows) {
    __shared__ float ssc[FDIM], ssh[FDIM];
    if (threadIdx.x < FDIM) {
        int c = threadIdx.x;
        float inv_n = 1.0f / (float)nrows;
        float mu  = bsum[c] * inv_n;
        float var = bsq[c] * inv_n - mu * mu;
        float sc  = g[c] * rsqrtf(var + BN_EPS);
        ssc[c] = sc;
        ssh[c] = b[c] - mu * sc;
    }
    __syncthreads();
    int idx = blockIdx.x * blockDim.x + threadIdx.x;   // over nrows*32 float4s
    if (idx >= nrows * 32) return;
    int c4 = (idx & 31) * 4;
    float4 xv = X[idx];
    float4 sc4 = *reinterpret_cast<const float4*>(&ssc[c4]);
    float4 sh4 = *reinterpret_cast<const float4*>(&ssh[c4]);
    float4 o;
    o.x = fmaxf(fmaf(xv.x, sc4.x, sh4.x), 0.f);
    o.y = fmaxf(fmaf(xv.y, sc4.y, sh4.y), 0.f);
    o.z = fmaxf(fmaf(xv.z, sc4.z, sh4.z), 0.f);
    o.w = fmaxf(fmaf(xv.w, sc4.w, sh4.w), 0.f);
    Y[idx] = o;
}

// ---------------- launch ----------------
extern "C" void kernel_launch(void* const* d_in, const int* in_sizes, int n_in,
                              void* d_out, int out_size) {
    const float* x     = (const float*)d_in[0];
    const int*   src   = (const int*)d_in[1];
    const int*   dst   = (const int*)d_in[2];
    const float* Wsrc0 = (const float*)d_in[3];  const float* bsrc0 = (const float*)d_in[4];
    const float* Wdst0 = (const float*)d_in[5];  const float* bdst0 = (const float*)d_in[6];
    const float* attn0 = (const float*)d_in[7];
    const float* Wres0 = (const float*)d_in[8];  const float* bres0 = (const float*)d_in[9];
    const float* Wsrc1 = (const float*)d_in[10]; const float* bsrc1 = (const float*)d_in[11];
    const float* Wdst1 = (const float*)d_in[12]; const float* bdst1 = (const float*)d_in[13];
    const float* attn1 = (const float*)d_in[14];
    const float* Wsrc2 = (const float*)d_in[15]; const float* bsrc2 = (const float*)d_in[16];
    const float* Wdst2 = (const float*)d_in[17]; const float* bdst2 = (const float*)d_in[18];
    const float* attn2 = (const float*)d_in[19];
    const float* Wres2 = (const float*)d_in[20]; const float* bres2 = (const float*)d_in[21];
    const float* g0    = (const float*)d_in[22]; const float* be0   = (const float*)d_in[23];
    const float* g1    = (const float*)d_in[24]; const float* be1   = (const float*)d_in[25];
    float* out = (float*)d_out;

    float *fs, *fd, *res, *hA, *hB, *bs0, *bq0, *bs1, *bq1;
    cudaGetSymbolAddress((void**)&fs,  g_fs);
    cudaGetSymbolAddress((void**)&fd,  g_fd);
    cudaGetSymbolAddress((void**)&res, g_res);
    cudaGetSymbolAddress((void**)&hA,  g_hA);
    cudaGetSymbolAddress((void**)&hB,  g_hB);
    cudaGetSymbolAddress((void**)&bs0, g_bnsum0);
    cudaGetSymbolAddress((void**)&bq0, g_bnsq0);
    cudaGetSymbolAddress((void**)&bs1, g_bnsum1);
    cudaGetSymbolAddress((void**)&bq1, g_bnsq1);

    const int N = NNODES, E = NEDGES;
    dim3 gL0((N + BM - 1) / BM, 2, 3);   // 3 mats, 128 cols
    dim3 gL1((N + BM - 1) / BM, 2, 2);   // 2 mats, 128 cols
    dim3 gL2((N + BM - 1) / BM, 3, 3);   // 3 mats, 188 cols
    int aggGrid = N / 8;                 // exactly 12500 (N % 8 == 0)
    int applyGrid = (N * 32 + 255) / 256;

    build_rowptr<<<(E + 255) / 256, 256>>>(dst, E, N);

    // ---- layer 0: x[N,100] -> 128, Linear residual ----
    gemm3_tf32<<<gL0, 256>>>(x, Wsrc0, Wdst0, Wres0, bsrc0, bdst0, bres0,
                             fs, fd, res, N, 100, 128);
    gat_agg128<<<aggGrid, 256>>>(fs, fd, attn0, res, hA, src, bs0, bq0, N);
    bn_apply<<<applyGrid, 256>>>((const float4*)hA, (float4*)hB, g0, be0, bs0, bq0, N);

    // ---- layer 1: 128 -> 128, Identity residual ----
    gemm3_tf32<<<gL1, 256>>>(hB, Wsrc1, Wdst1, Wdst1, bsrc1, bdst1, bdst1,
                             fs, fd, fd, N, 128, 128);
    gat_agg128<<<aggGrid, 256>>>(fs, fd, attn1, hB, hA, src, bs1, bq1, N);
    bn_apply<<<applyGrid, 256>>>((const float4*)hA, (float4*)hB, g1, be1, bs1, bq1, N);

    // ---- layer 2: 128 -> 188 (H=4, C=47), Linear residual; mean heads + log_softmax ----
    gemm3_tf32<<<gL2, 256>>>(hB, Wsrc2, Wdst2, Wres2, bsrc2, bdst2, bres2,
                             fs, fd, res, N, 128, 188);
    gat_agg_final<<<aggGrid, 256>>>(fs, fd, attn2, res, out, src, N);
}

// round 14
// speedup vs baseline: 1.4836x; 1.4836x over previous
#include <cuda_runtime.h>
#include <stdint.h>
#include <math.h>

#define NNODES 100000
#define NEDGES 1000000
#define FDIM   128
#define F2DIM  188
#define NCLS   47
#define NHEAD  4
#define BN_EPS 1e-5f

// ---------------- scratch (device globals; no allocation allowed) ----------------
__device__ float g_fs[(size_t)NNODES * F2DIM];
__device__ float g_fd[(size_t)NNODES * F2DIM];
__device__ float g_res[(size_t)NNODES * F2DIM];
__device__ float g_hA[(size_t)NNODES * FDIM];
__device__ float g_hB[(size_t)NNODES * FDIM];
__device__ int   g_rowptr[NNODES + 1];
__device__ float g_bnsum0[FDIM];
__device__ float g_bnsq0[FDIM];
__device__ float g_bnsum1[FDIM];
__device__ float g_bnsq1[FDIM];

// ---------------- CSR row_ptr from sorted dst (+ zero BN accumulators) ----------------
__global__ void build_rowptr(const int* __restrict__ dst, int E, int N) {
    int e = blockIdx.x * blockDim.x + threadIdx.x;
    if (blockIdx.x == 0 && threadIdx.x < FDIM) {
        g_bnsum0[threadIdx.x] = 0.f; g_bnsq0[threadIdx.x] = 0.f;
        g_bnsum1[threadIdx.x] = 0.f; g_bnsq1[threadIdx.x] = 0.f;
    }
    if (e >= E) return;
    int d = dst[e];
    int dprev = (e == 0) ? -1 : dst[e - 1];
    for (int n = dprev + 1; n <= d; n++) g_rowptr[n] = e;
    if (e == E - 1) {
        for (int n = d + 1; n <= N; n++) g_rowptr[n] = E;
    }
}

// ---------------- cp.async helpers ----------------
__device__ __forceinline__ void cp_async16(uint32_t smem_addr, const void* gptr, int src_bytes) {
    asm volatile("cp.async.cg.shared.global [%0], [%1], 16, %2;\n"
                 :: "r"(smem_addr), "l"(gptr), "r"(src_bytes));
}
__device__ __forceinline__ void cp_commit() {
    asm volatile("cp.async.commit_group;\n");
}
template <int NN>
__device__ __forceinline__ void cp_wait() {
    asm volatile("cp.async.wait_group %0;\n" :: "n"(NN));
}

// ---------------- split-tf32 tensor-core GEMM, cp.async double-buffered ----------------
// R10-proven config (measured inside the 1083us best): block 128x64, BK=16,
// 256 threads (8 warps, warp tile 32x32), 2 stages, 2 syncs/iter, 95 regs.
// blockIdx.z selects among up to 3 weight matrices sharing the same A.

#define BM 128
#define BNT 64
#define BKT 16
#define APAD 20    // A row stride (floats)
#define BSTR 72    // B row stride

__device__ __forceinline__ float tf32_rna(float x) {
    float r;
    asm("cvt.rna.tf32.f32 %0, %1;" : "=f"(r) : "f"(x));
    return r;
}

__device__ __forceinline__ void mma_tf32(float* d, const float* a, const float* b) {
    asm volatile(
        "mma.sync.aligned.m16n8k8.row.col.f32.tf32.tf32.f32 "
        "{%0,%1,%2,%3}, {%4,%5,%6,%7}, {%8,%9}, {%0,%1,%2,%3};"
        : "+f"(d[0]), "+f"(d[1]), "+f"(d[2]), "+f"(d[3])
        : "r"(__float_as_uint(a[0])), "r"(__float_as_uint(a[1])),
          "r"(__float_as_uint(a[2])), "r"(__float_as_uint(a[3])),
          "r"(__float_as_uint(b[0])), "r"(__float_as_uint(b[1])));
}

__global__ __launch_bounds__(256, 2)
void gemm3_tf32(const float* __restrict__ A,
                const float* __restrict__ W0, const float* __restrict__ W1, const float* __restrict__ W2,
                const float* __restrict__ b0, const float* __restrict__ b1, const float* __restrict__ b2,
                float* __restrict__ C0, float* __restrict__ C1, float* __restrict__ C2,
                int nrows, int K, int ncols) {
    __shared__ float As[2][BM][APAD];
    __shared__ float Bs[2][BKT][BSTR];

    int z = blockIdx.z;
    const float* W    = (z == 0) ? W0 : ((z == 1) ? W1 : W2);
    const float* bias = (z == 0) ? b0 : ((z == 1) ? b1 : b2);
    float* C          = (z == 0) ? C0 : ((z == 1) ? C1 : C2);

    int tid = threadIdx.x;
    int warp = tid >> 5, lane = tid & 31;
    int wm = warp & 3;
    int wn = warp >> 2;
    int g = lane >> 2, t4 = lane & 3;
    int row0 = blockIdx.x * BM;
    int col0 = blockIdx.y * BNT;

    int a_row = tid >> 1;              // 0..127
    int a_kc  = (tid & 1) * 8;         // 0 or 8
    int b_kr  = tid >> 4;              // 0..15
    int b_nc  = (tid & 15) * 4;        // 0..60

    int arow_g = row0 + a_row;
    bool arow_ok = arow_g < nrows;
    const float* Arow = A + (size_t)(arow_ok ? arow_g : 0) * K;
    bool bcol_ok = (col0 + b_nc) < ncols;

    float acc[2][4][4];
#pragma unroll
    for (int mt = 0; mt < 2; mt++)
#pragma unroll
        for (int nt = 0; nt < 4; nt++)
#pragma unroll
            for (int r = 0; r < 4; r++) acc[mt][nt][r] = 0.f;

    int niter = (K + BKT - 1) / BKT;

    uint32_t sA0 = (uint32_t)__cvta_generic_to_shared(&As[0][a_row][a_kc]);
    uint32_t sA1 = (uint32_t)__cvta_generic_to_shared(&As[1][a_row][a_kc]);
    uint32_t sB0 = (uint32_t)__cvta_generic_to_shared(&Bs[0][b_kr][b_nc]);
    uint32_t sB1 = (uint32_t)__cvta_generic_to_shared(&Bs[1][b_kr][b_nc]);

    auto prefetch = [&](int stage, int k0) {
        uint32_t sA = stage ? sA1 : sA0;
        uint32_t sB = stage ? sB1 : sB0;
#pragma unroll
        for (int q = 0; q < 2; q++) {
            int kk = k0 + a_kc + 4 * q;
            int bytes = (arow_ok && (kk + 4 <= K)) ? 16 : 0;
            cp_async16(sA + 16 * q, Arow + (bytes ? kk : 0), bytes);
        }
        {
            int kk = k0 + b_kr;
            int bytes = (bcol_ok && kk < K) ? 16 : 0;
            const float* src = W + (size_t)(bytes ? kk : 0) * ncols + col0 + (bytes ? b_nc : 0);
            cp_async16(sB, src, bytes);
        }
    };

    prefetch(0, 0);
    cp_commit();

    int buf = 0;
    for (int it = 0; it < niter; it++) {
        if (it + 1 < niter) prefetch(buf ^ 1, (it + 1) * BKT);
        cp_commit();
        cp_wait<1>();
        __syncthreads();

#pragma unroll
        for (int ks = 0; ks < 2; ks++) {
            int kb = ks * 8;
            float ah[2][4], al[2][4];
#pragma unroll
            for (int mt = 0; mt < 2; mt++) {
                int mr = wm * 32 + mt * 16 + g;
                float r0 = As[buf][mr][kb + t4];
                float r1 = As[buf][mr + 8][kb + t4];
                float r2 = As[buf][mr][kb + t4 + 4];
                float r3 = As[buf][mr + 8][kb + t4 + 4];
                ah[mt][0] = tf32_rna(r0); al[mt][0] = tf32_rna(r0 - ah[mt][0]);
                ah[mt][1] = tf32_rna(r1); al[mt][1] = tf32_rna(r1 - ah[mt][1]);
                ah[mt][2] = tf32_rna(r2); al[mt][2] = tf32_rna(r2 - ah[mt][2]);
                ah[mt][3] = tf32_rna(r3); al[mt][3] = tf32_rna(r3 - ah[mt][3]);
            }
            float bh[4][2], bl[4][2];
#pragma unroll
            for (int nt = 0; nt < 4; nt++) {
                int nc = wn * 32 + nt * 8 + g;
                float r0 = Bs[buf][kb + t4][nc];
                float r1 = Bs[buf][kb + t4 + 4][nc];
                bh[nt][0] = tf32_rna(r0); bl[nt][0] = tf32_rna(r0 - bh[nt][0]);
                bh[nt][1] = tf32_rna(r1); bl[nt][1] = tf32_rna(r1 - bh[nt][1]);
            }
#pragma unroll
            for (int mt = 0; mt < 2; mt++)
#pragma unroll
                for (int nt = 0; nt < 4; nt++) {
                    mma_tf32(acc[mt][nt], ah[mt], bh[nt]);
                    mma_tf32(acc[mt][nt], ah[mt], bl[nt]);
                    mma_tf32(acc[mt][nt], al[mt], bh[nt]);
                }
        }
        __syncthreads();
        buf ^= 1;
    }

    // ---- epilogue: bias add + store ----
#pragma unroll
    for (int mt = 0; mt < 2; mt++) {
#pragma unroll
        for (int nt = 0; nt < 4; nt++) {
            int row = row0 + wm * 32 + mt * 16 + g;
            int col = col0 + wn * 32 + nt * 8 + 2 * t4;
            if (col < ncols) {
                float b0v = bias[col], b1v = bias[col + 1];
                if (row < nrows) {
                    float2 v = make_float2(acc[mt][nt][0] + b0v, acc[mt][nt][1] + b1v);
                    *reinterpret_cast<float2*>(C + (size_t)row * ncols + col) = v;
                }
                if (row + 8 < nrows) {
                    float2 v = make_float2(acc[mt][nt][2] + b0v, acc[mt][nt][3] + b1v);
                    *reinterpret_cast<float2*>(C + (size_t)(row + 8) * ncols + col) = v;
                }
            }
        }
    }
}

// ---------------- GATv2 aggregation, F=128 (H=4, D=32), fused BN-stats ----------------
// Warp per node; lane owns a float4 chunk. 2-edge unroll.
// REQUIRES: grid*8 == N exactly (all warps live through __syncthreads).
__global__ void gat_agg128(const float* __restrict__ fs, const float* __restrict__ fd,
                           const float* __restrict__ attn, const float* __restrict__ res,
                           float* __restrict__ out, const int* __restrict__ srcidx,
                           float* __restrict__ bsum, float* __restrict__ bsq, int N) {
    __shared__ float sred[8][256];   // per-warp: [0..127]=val, [128..255]=val^2

    int wid  = threadIdx.x >> 5;
    int lane = threadIdx.x & 31;
    int n = blockIdx.x * 8 + wid;    // n < N by construction

    const float4* fs4   = (const float4*)fs;
    const float4* fd4   = (const float4*)fd;
    const float4* attn4 = (const float4*)attn;
    const float4* res4  = (const float4*)res;
    float4* out4 = (float4*)out;

    float4 fdv = fd4[(size_t)n * 32 + lane];
    float4 av  = attn4[lane];
    float4 acc = make_float4(0.f, 0.f, 0.f, 0.f);
    float m = -1e30f, s = 0.f;

    int e0 = g_rowptr[n], e1 = g_rowptr[n + 1];
    float4 f0 = make_float4(0.f, 0.f, 0.f, 0.f);
    float4 f1 = f0;
    if (e0 < e1)     f0 = __ldg(&fs4[(size_t)__ldg(&srcidx[e0]) * 32 + lane]);
    if (e0 + 1 < e1) f1 = __ldg(&fs4[(size_t)__ldg(&srcidx[e0 + 1]) * 32 + lane]);

    for (int e = e0; e < e1; e += 2) {
        float4 c0 = f0, c1 = f1;
        bool v1 = (e + 1) < e1;
        if (e + 2 < e1) f0 = __ldg(&fs4[(size_t)__ldg(&srcidx[e + 2]) * 32 + lane]);
        if (e + 3 < e1) f1 = __ldg(&fs4[(size_t)__ldg(&srcidx[e + 3]) * 32 + lane]);

        float ax, ay, az, aw;
        ax = c0.x + fdv.x; ax = (ax > 0.f) ? ax : 0.2f * ax;
        ay = c0.y + fdv.y; ay = (ay > 0.f) ? ay : 0.2f * ay;
        az = c0.z + fdv.z; az = (az > 0.f) ? az : 0.2f * az;
        aw = c0.w + fdv.w; aw = (aw > 0.f) ? aw : 0.2f * aw;
        float t0 = ax * av.x + ay * av.y + az * av.z + aw * av.w;

        ax = c1.x + fdv.x; ax = (ax > 0.f) ? ax : 0.2f * ax;
        ay = c1.y + fdv.y; ay = (ay > 0.f) ? ay : 0.2f * ay;
        az = c1.z + fdv.z; az = (az > 0.f) ? az : 0.2f * az;
        aw = c1.w + fdv.w; aw = (aw > 0.f) ? aw : 0.2f * aw;
        float t1 = ax * av.x + ay * av.y + az * av.z + aw * av.w;

        t0 += __shfl_xor_sync(0xffffffffu, t0, 4);
        t1 += __shfl_xor_sync(0xffffffffu, t1, 4);
        t0 += __shfl_xor_sync(0xffffffffu, t0, 2);
        t1 += __shfl_xor_sync(0xffffffffu, t1, 2);
        t0 += __shfl_xor_sync(0xffffffffu, t0, 1);
        t1 += __shfl_xor_sync(0xffffffffu, t1, 1);

        if (t0 > m) {
            float c = __expf(m - t0);
            acc.x *= c; acc.y *= c; acc.z *= c; acc.w *= c;
            s *= c; m = t0;
        }
        float p0 = __expf(t0 - m);
        s += p0;
        acc.x = fmaf(p0, c0.x, acc.x);
        acc.y = fmaf(p0, c0.y, acc.y);
        acc.z = fmaf(p0, c0.z, acc.z);
        acc.w = fmaf(p0, c0.w, acc.w);

        if (v1) {
            if (t1 > m) {
                float c = __expf(m - t1);
                acc.x *= c; acc.y *= c; acc.z *= c; acc.w *= c;
                s *= c; m = t1;
            }
            float p1 = __expf(t1 - m);
            s += p1;
            acc.x = fmaf(p1, c1.x, acc.x);
            acc.y = fmaf(p1, c1.y, acc.y);
            acc.z = fmaf(p1, c1.z, acc.z);
            acc.w = fmaf(p1, c1.w, acc.w);
        }
    }
    float inv = (e1 > e0) ? (1.f / s) : 0.f;
    float4 r = res4[(size_t)n * 32 + lane];
    float4 o;
    o.x = fmaxf(fmaf(acc.x, inv, r.x), 0.f);
    o.y = fmaxf(fmaf(acc.y, inv, r.y), 0.f);
    o.z = fmaxf(fmaf(acc.z, inv, r.z), 0.f);
    o.w = fmaxf(fmaf(acc.w, inv, r.w), 0.f);
    out4[(size_t)n * 32 + lane] = o;

    // ---- fused BN statistics ----
    int c4 = lane * 4;
    sred[wid][c4 + 0] = o.x;  sred[wid][128 + c4 + 0] = o.x * o.x;
    sred[wid][c4 + 1] = o.y;  sred[wid][128 + c4 + 1] = o.y * o.y;
    sred[wid][c4 + 2] = o.z;  sred[wid][128 + c4 + 2] = o.z * o.z;
    sred[wid][c4 + 3] = o.w;  sred[wid][128 + c4 + 3] = o.w * o.w;
    __syncthreads();
    int t = threadIdx.x;
    if (t < 128) {
        float ss = 0.f, qq = 0.f;
#pragma unroll
        for (int w = 0; w < 8; w++) {
            ss += sred[w][t];
            qq += sred[w][128 + t];
        }
        atomicAdd(&bsum[t], ss);
        atomicAdd(&bsq[t], qq);
    }
}

// ---------------- Layer-2 aggregation (C=47) + head-mean + log_softmax ----------------
__global__ void gat_agg_final(const float* __restrict__ fs, const float* __restrict__ fd,
                              const float* __restrict__ attn, const float* __restrict__ res,
                              float* __restrict__ out, const int* __restrict__ srcidx, int N) {
    int warp = (blockIdx.x * blockDim.x + threadIdx.x) >> 5;
    int lane = threadIdx.x & 31;
    if (warp >= N) return;
    int n = warp;
    int h = lane >> 3, sub = lane & 7;
    int c0i = sub * 6;
    int cnt = (47 - c0i < 6) ? (47 - c0i) : 6;   // 6 or 5
    int base = h * 47 + c0i;

    float fdv[6], av[6], acc[6];
#pragma unroll
    for (int j = 0; j < 6; j++) {
        bool valid = j < cnt;
        fdv[j] = valid ? fd[(size_t)n * 188 + base + j] : 0.f;
        av[j]  = valid ? attn[base + j] : 0.f;
        acc[j] = 0.f;
    }
    float m = -1e30f, s = 0.f;

    int e0 = g_rowptr[n], e1 = g_rowptr[n + 1];
    float f0[6], f1[6];
#pragma unroll
    for (int j = 0; j < 6; j++) { f0[j] = 0.f; f1[j] = 0.f; }
    if (e0 < e1) {
        const float* p = fs + (size_t)__ldg(&srcidx[e0]) * 188 + base;
#pragma unroll
        for (int j = 0; j < 6; j++) if (j < cnt) f0[j] = __ldg(&p[j]);
    }
    if (e0 + 1 < e1) {
        const float* p = fs + (size_t)__ldg(&srcidx[e0 + 1]) * 188 + base;
#pragma unroll
        for (int j = 0; j < 6; j++) if (j < cnt) f1[j] = __ldg(&p[j]);
    }

    for (int e = e0; e < e1; e += 2) {
        float c0[6], c1[6];
#pragma unroll
        for (int j = 0; j < 6; j++) { c0[j] = f0[j]; c1[j] = f1[j]; }
        bool v1 = (e + 1) < e1;
        if (e + 2 < e1) {
            const float* p = fs + (size_t)__ldg(&srcidx[e + 2]) * 188 + base;
#pragma unroll
            for (int j = 0; j < 6; j++) if (j < cnt) f0[j] = __ldg(&p[j]);
        }
        if (e + 3 < e1) {
            const float* p = fs + (size_t)__ldg(&srcidx[e + 3]) * 188 + base;
#pragma unroll
            for (int j = 0; j < 6; j++) if (j < cnt) f1[j] = __ldg(&p[j]);
        }

        float t0 = 0.f, t1 = 0.f;
#pragma unroll
        for (int j = 0; j < 6; j++) {
            float v = c0[j] + fdv[j];
            v = (v > 0.f) ? v : 0.2f * v;
            t0 = fmaf(v, av[j], t0);
        }
#pragma unroll
        for (int j = 0; j < 6; j++) {
            float v = c1[j] + fdv[j];
            v = (v > 0.f) ? v : 0.2f * v;
            t1 = fmaf(v, av[j], t1);
        }
        t0 += __shfl_xor_sync(0xffffffffu, t0, 4);
        t1 += __shfl_xor_sync(0xffffffffu, t1, 4);
        t0 += __shfl_xor_sync(0xffffffffu, t0, 2);
        t1 += __shfl_xor_sync(0xffffffffu, t1, 2);
        t0 += __shfl_xor_sync(0xffffffffu, t0, 1);
        t1 += __shfl_xor_sync(0xffffffffu, t1, 1);

        if (t0 > m) {
            float c = __expf(m - t0);
#pragma unroll
            for (int j = 0; j < 6; j++) acc[j] *= c;
            s *= c; m = t0;
        }
        float p0 = __expf(t0 - m);
        s += p0;
#pragma unroll
        for (int j = 0; j < 6; j++) acc[j] = fmaf(p0, c0[j], acc[j]);

        if (v1) {
            if (t1 > m) {
                float c = __expf(m - t1);
#pragma unroll
                for (int j = 0; j < 6; j++) acc[j] *= c;
                s *= c; m = t1;
            }
            float p1 = __expf(t1 - m);
            s += p1;
#pragma unroll
            for (int j = 0; j < 6; j++) acc[j] = fmaf(p1, c1[j], acc[j]);
        }
    }

    float inv = (e1 > e0) ? (1.f / s) : 0.f;
    float v[6];
#pragma unroll
    for (int j = 0; j < 6; j++) {
        float rr = (j < cnt) ? res[(size_t)n * 188 + base + j] : 0.f;
        v[j] = fmaf(acc[j], inv, rr);
    }
#pragma unroll
    for (int j = 0; j < 6; j++) {
        v[j] += __shfl_xor_sync(0xffffffffu, v[j], 8);
        v[j] += __shfl_xor_sync(0xffffffffu, v[j], 16);
        v[j] *= 0.25f;
    }
    float lm = -1e30f;
#pragma unroll
    for (int j = 0; j < 6; j++) if (j < cnt) lm = fmaxf(lm, v[j]);
    lm = fmaxf(lm, __shfl_xor_sync(0xffffffffu, lm, 4));
    lm = fmaxf(lm, __shfl_xor_sync(0xffffffffu, lm, 2));
    lm = fmaxf(lm, __shfl_xor_sync(0xffffffffu, lm, 1));
    float ls = 0.f;
#pragma unroll
    for (int j = 0; j < 6; j++) if (j < cnt) ls += __expf(v[j] - lm);
    ls += __shfl_xor_sync(0xffffffffu, ls, 4);
    ls += __shfl_xor_sync(0xffffffffu, ls, 2);
    ls += __shfl_xor_sync(0xffffffffu, ls, 1);
    float lse = lm + logf(ls);
    if (h == 0) {
#pragma unroll
        for (int j = 0; j < 6; j++)
            if (j < cnt) out[(size_t)n * 47 + c0i + j] = v[j] - lse;
    }
}

// ---------------- BatchNorm apply: smem-precomputed scale/shift, relu fused ----------------
__global__ void bn_apply(const float4* __restrict__ X, float4* __restrict__ Y,
                         const float* __restrict__ g, const float* __restrict__ b,
                         const float* __restrict__ bsum, const float* __restrict__ bsq, int nrows) {
    __shared__ float ssc[FDIM], ssh[FDIM];
    if (threadIdx.x < FDIM) {
        int c = threadIdx.x;
        float inv_n = 1.0f / (float)nrows;
        float mu  = bsum[c] * inv_n;
        float var = bsq[c] * inv_n - mu * mu;
        float sc  = g[c] * rsqrtf(var + BN_EPS);
        ssc[c] = sc;
        ssh[c] = b[c] - mu * sc;
    }
    __syncthreads();
    int idx = blockIdx.x * blockDim.x + threadIdx.x;   // over nrows*32 float4s
    if (idx >= nrows * 32) return;
    int c4 = (idx & 31) * 4;
    float4 xv = X[idx];
    float4 sc4 = *reinterpret_cast<const float4*>(&ssc[c4]);
    float4 sh4 = *reinterpret_cast<const float4*>(&ssh[c4]);
    float4 o;
    o.x = fmaxf(fmaf(xv.x, sc4.x, sh4.x), 0.f);
    o.y = fmaxf(fmaf(xv.y, sc4.y, sh4.y), 0.f);
    o.z = fmaxf(fmaf(xv.z, sc4.z, sh4.z), 0.f);
    o.w = fmaxf(fmaf(xv.w, sc4.w, sh4.w), 0.f);
    Y[idx] = o;
}

// ---------------- launch ----------------
extern "C" void kernel_launch(void* const* d_in, const int* in_sizes, int n_in,
                              void* d_out, int out_size) {
    const float* x     = (const float*)d_in[0];
    const int*   src   = (const int*)d_in[1];
    const int*   dst   = (const int*)d_in[2];
    const float* Wsrc0 = (const float*)d_in[3];  const float* bsrc0 = (const float*)d_in[4];
    const float* Wdst0 = (const float*)d_in[5];  const float* bdst0 = (const float*)d_in[6];
    const float* attn0 = (const float*)d_in[7];
    const float* Wres0 = (const float*)d_in[8];  const float* bres0 = (const float*)d_in[9];
    const float* Wsrc1 = (const float*)d_in[10]; const float* bsrc1 = (const float*)d_in[11];
    const float* Wdst1 = (const float*)d_in[12]; const float* bdst1 = (const float*)d_in[13];
    const float* attn1 = (const float*)d_in[14];
    const float* Wsrc2 = (const float*)d_in[15]; const float* bsrc2 = (const float*)d_in[16];
    const float* Wdst2 = (const float*)d_in[17]; const float* bdst2 = (const float*)d_in[18];
    const float* attn2 = (const float*)d_in[19];
    const float* Wres2 = (const float*)d_in[20]; const float* bres2 = (const float*)d_in[21];
    const float* g0    = (const float*)d_in[22]; const float* be0   = (const float*)d_in[23];
    const float* g1    = (const float*)d_in[24]; const float* be1   = (const float*)d_in[25];
    float* out = (float*)d_out;

    float *fs, *fd, *res, *hA, *hB, *bs0, *bq0, *bs1, *bq1;
    cudaGetSymbolAddress((void**)&fs,  g_fs);
    cudaGetSymbolAddress((void**)&fd,  g_fd);
    cudaGetSymbolAddress((void**)&res, g_res);
    cudaGetSymbolAddress((void**)&hA,  g_hA);
    cudaGetSymbolAddress((void**)&hB,  g_hB);
    cudaGetSymbolAddress((void**)&bs0, g_bnsum0);
    cudaGetSymbolAddress((void**)&bq0, g_bnsq0);
    cudaGetSymbolAddress((void**)&bs1, g_bnsum1);
    cudaGetSymbolAddress((void**)&bq1, g_bnsq1);

    const int N = NNODES, E = NEDGES;
    dim3 gL0((N + BM - 1) / BM, 2, 3);   // 3 mats, 128 cols
    dim3 gL1((N + BM - 1) / BM, 2, 2);   // 2 mats, 128 cols
    dim3 gL2((N + BM - 1) / BM, 3, 3);   // 3 mats, 188 cols
    int aggGrid = N / 8;                 // exactly 12500 (N % 8 == 0)
    int applyGrid = (N * 32 + 255) / 256;

    build_rowptr<<<(E + 255) / 256, 256>>>(dst, E, N);

    // ---- layer 0: x[N,100] -> 128, Linear residual ----
    gemm3_tf32<<<gL0, 256>>>(x, Wsrc0, Wdst0, Wres0, bsrc0, bdst0, bres0,
                             fs, fd, res, N, 100, 128);
    gat_agg128<<<aggGrid, 256>>>(fs, fd, attn0, res, hA, src, bs0, bq0, N);
    bn_apply<<<applyGrid, 256>>>((const float4*)hA, (float4*)hB, g0, be0, bs0, bq0, N);

    // ---- layer 1: 128 -> 128, Identity residual ----
    gemm3_tf32<<<gL1, 256>>>(hB, Wsrc1, Wdst1, Wdst1, bsrc1, bdst1, bdst1,
                             fs, fd, fd, N, 128, 128);
    gat_agg128<<<aggGrid, 256>>>(fs, fd, attn1, hB, hA, src, bs1, bq1, N);
    bn_apply<<<applyGrid, 256>>>((const float4*)hA, (float4*)hB, g1, be1, bs1, bq1, N);

    // ---- layer 2: 128 -> 188 (H=4, C=47), Linear residual; mean heads + log_softmax ----
    gemm3_tf32<<<gL2, 256>>>(hB, Wsrc2, Wdst2, Wres2, bsrc2, bdst2, bres2,
                             fs, fd, res, N, 128, 188);
    gat_agg_final<<<aggGrid, 256>>>(fs, fd, attn2, res, out, src, N);
}

// round 15
// speedup vs baseline: 1.8811x; 1.2679x over previous
#include <cuda_runtime.h>
#include <stdint.h>
#include <math.h>

#define NNODES 100000
#define NEDGES 1000000
#define FDIM   128
#define F2DIM  188
#define NCLS   47
#define NHEAD  4
#define BN_EPS 1e-5f

// ---------------- scratch (device globals; no allocation allowed) ----------------
__device__ float g_fs[(size_t)NNODES * F2DIM];
__device__ float g_fd[(size_t)NNODES * F2DIM];
__device__ float g_res[(size_t)NNODES * F2DIM];
__device__ float g_hA[(size_t)NNODES * FDIM];
__device__ float g_hB[(size_t)NNODES * FDIM];
__device__ int   g_rowptr[NNODES + 1];
__device__ float g_bnsum0[FDIM];
__device__ float g_bnsq0[FDIM];
__device__ float g_bnsum1[FDIM];
__device__ float g_bnsq1[FDIM];

// ---------------- CSR row_ptr from sorted dst (+ zero BN accumulators) ----------------
__global__ void build_rowptr(const int* __restrict__ dst, int E, int N) {
    int e = blockIdx.x * blockDim.x + threadIdx.x;
    if (blockIdx.x == 0 && threadIdx.x < FDIM) {
        g_bnsum0[threadIdx.x] = 0.f; g_bnsq0[threadIdx.x] = 0.f;
        g_bnsum1[threadIdx.x] = 0.f; g_bnsq1[threadIdx.x] = 0.f;
    }
    if (e >= E) return;
    int d = dst[e];
    int dprev = (e == 0) ? -1 : dst[e - 1];
    for (int n = dprev + 1; n <= d; n++) g_rowptr[n] = e;
    if (e == E - 1) {
        for (int n = d + 1; n <= N; n++) g_rowptr[n] = E;
    }
}

// ---------------- cp.async helpers ----------------
__device__ __forceinline__ void cp_async16(uint32_t smem_addr, const void* gptr, int src_bytes) {
    asm volatile("cp.async.cg.shared.global [%0], [%1], 16, %2;\n"
                 :: "r"(smem_addr), "l"(gptr), "r"(src_bytes));
}
__device__ __forceinline__ void cp_commit() {
    asm volatile("cp.async.commit_group;\n");
}
template <int NN>
__device__ __forceinline__ void cp_wait() {
    asm volatile("cp.async.wait_group %0;\n" :: "n"(NN));
}

// ---------------- tf32 tensor-core GEMM, cp.async double-buffered ----------------
// Structure identical to the proven R10/R14 kernel; single-MMA plain tf32
// (accuracy budget: ~1e-4 end-to-end vs 1e-3 threshold).
// Tile: block 128x64, BK=16, 256 threads (8 warps, warp tile 32x32).
// blockIdx.z selects among up to 3 weight matrices sharing the same A.

#define BM 128
#define BNT 64
#define BKT 16
#define APAD 20    // A row stride (floats)
#define BSTR 72    // B row stride

__device__ __forceinline__ float tf32_rna(float x) {
    float r;
    asm("cvt.rna.tf32.f32 %0, %1;" : "=f"(r) : "f"(x));
    return r;
}

__device__ __forceinline__ void mma_tf32(float* d, const float* a, const float* b) {
    asm volatile(
        "mma.sync.aligned.m16n8k8.row.col.f32.tf32.tf32.f32 "
        "{%0,%1,%2,%3}, {%4,%5,%6,%7}, {%8,%9}, {%0,%1,%2,%3};"
        : "+f"(d[0]), "+f"(d[1]), "+f"(d[2]), "+f"(d[3])
        : "r"(__float_as_uint(a[0])), "r"(__float_as_uint(a[1])),
          "r"(__float_as_uint(a[2])), "r"(__float_as_uint(a[3])),
          "r"(__float_as_uint(b[0])), "r"(__float_as_uint(b[1])));
}

__global__ __launch_bounds__(256, 2)
void gemm3_tf32(const float* __restrict__ A,
                const float* __restrict__ W0, const float* __restrict__ W1, const float* __restrict__ W2,
                const float* __restrict__ b0, const float* __restrict__ b1, const float* __restrict__ b2,
                float* __restrict__ C0, float* __restrict__ C1, float* __restrict__ C2,
                int nrows, int K, int ncols) {
    __shared__ float As[2][BM][APAD];
    __shared__ float Bs[2][BKT][BSTR];

    int z = blockIdx.z;
    const float* W    = (z == 0) ? W0 : ((z == 1) ? W1 : W2);
    const float* bias = (z == 0) ? b0 : ((z == 1) ? b1 : b2);
    float* C          = (z == 0) ? C0 : ((z == 1) ? C1 : C2);

    int tid = threadIdx.x;
    int warp = tid >> 5, lane = tid & 31;
    int wm = warp & 3;
    int wn = warp >> 2;
    int g = lane >> 2, t4 = lane & 3;
    int row0 = blockIdx.x * BM;
    int col0 = blockIdx.y * BNT;

    int a_row = tid >> 1;              // 0..127
    int a_kc  = (tid & 1) * 8;         // 0 or 8
    int b_kr  = tid >> 4;              // 0..15
    int b_nc  = (tid & 15) * 4;        // 0..60

    int arow_g = row0 + a_row;
    bool arow_ok = arow_g < nrows;
    const float* Arow = A + (size_t)(arow_ok ? arow_g : 0) * K;
    bool bcol_ok = (col0 + b_nc) < ncols;

    float acc[2][4][4];
#pragma unroll
    for (int mt = 0; mt < 2; mt++)
#pragma unroll
        for (int nt = 0; nt < 4; nt++)
#pragma unroll
            for (int r = 0; r < 4; r++) acc[mt][nt][r] = 0.f;

    int niter = (K + BKT - 1) / BKT;

    uint32_t sA0 = (uint32_t)__cvta_generic_to_shared(&As[0][a_row][a_kc]);
    uint32_t sA1 = (uint32_t)__cvta_generic_to_shared(&As[1][a_row][a_kc]);
    uint32_t sB0 = (uint32_t)__cvta_generic_to_shared(&Bs[0][b_kr][b_nc]);
    uint32_t sB1 = (uint32_t)__cvta_generic_to_shared(&Bs[1][b_kr][b_nc]);

    auto prefetch = [&](int stage, int k0) {
        uint32_t sA = stage ? sA1 : sA0;
        uint32_t sB = stage ? sB1 : sB0;
#pragma unroll
        for (int q = 0; q < 2; q++) {
            int kk = k0 + a_kc + 4 * q;
            int bytes = (arow_ok && (kk + 4 <= K)) ? 16 : 0;
            cp_async16(sA + 16 * q, Arow + (bytes ? kk : 0), bytes);
        }
        {
            int kk = k0 + b_kr;
            int bytes = (bcol_ok && kk < K) ? 16 : 0;
            const float* src = W + (size_t)(bytes ? kk : 0) * ncols + col0 + (bytes ? b_nc : 0);
            cp_async16(sB, src, bytes);
        }
    };

    prefetch(0, 0);
    cp_commit();

    int buf = 0;
    for (int it = 0; it < niter; it++) {
        if (it + 1 < niter) prefetch(buf ^ 1, (it + 1) * BKT);
        cp_commit();
        cp_wait<1>();
        __syncthreads();

#pragma unroll
        for (int ks = 0; ks < 2; ks++) {
            int kb = ks * 8;
            float ah[2][4];
#pragma unroll
            for (int mt = 0; mt < 2; mt++) {
                int mr = wm * 32 + mt * 16 + g;
                ah[mt][0] = tf32_rna(As[buf][mr][kb + t4]);
                ah[mt][1] = tf32_rna(As[buf][mr + 8][kb + t4]);
                ah[mt][2] = tf32_rna(As[buf][mr][kb + t4 + 4]);
                ah[mt][3] = tf32_rna(As[buf][mr + 8][kb + t4 + 4]);
            }
            float bh[4][2];
#pragma unroll
            for (int nt = 0; nt < 4; nt++) {
                int nc = wn * 32 + nt * 8 + g;
                bh[nt][0] = tf32_rna(Bs[buf][kb + t4][nc]);
                bh[nt][1] = tf32_rna(Bs[buf][kb + t4 + 4][nc]);
            }
#pragma unroll
            for (int mt = 0; mt < 2; mt++)
#pragma unroll
                for (int nt = 0; nt < 4; nt++)
                    mma_tf32(acc[mt][nt], ah[mt], bh[nt]);
        }
        __syncthreads();
        buf ^= 1;
    }

    // ---- epilogue: bias add + store ----
#pragma unroll
    for (int mt = 0; mt < 2; mt++) {
#pragma unroll
        for (int nt = 0; nt < 4; nt++) {
            int row = row0 + wm * 32 + mt * 16 + g;
            int col = col0 + wn * 32 + nt * 8 + 2 * t4;
            if (col < ncols) {
                float b0v = bias[col], b1v = bias[col + 1];
                if (row < nrows) {
                    float2 v = make_float2(acc[mt][nt][0] + b0v, acc[mt][nt][1] + b1v);
                    *reinterpret_cast<float2*>(C + (size_t)row * ncols + col) = v;
                }
                if (row + 8 < nrows) {
                    float2 v = make_float2(acc[mt][nt][2] + b0v, acc[mt][nt][3] + b1v);
                    *reinterpret_cast<float2*>(C + (size_t)(row + 8) * ncols + col) = v;
                }
            }
        }
    }
}

// ---------------- GATv2 aggregation, F=128 (H=4, D=32), fused BN-stats ----------------
// Warp per node; lane owns a float4 chunk. 2-edge unroll.
// REQUIRES: grid*8 == N exactly (all warps live through __syncthreads).
__global__ void gat_agg128(const float* __restrict__ fs, const float* __restrict__ fd,
                           const float* __restrict__ attn, const float* __restrict__ res,
                           float* __restrict__ out, const int* __restrict__ srcidx,
                           float* __restrict__ bsum, float* __restrict__ bsq, int N) {
    __shared__ float sred[8][256];   // per-warp: [0..127]=val, [128..255]=val^2

    int wid  = threadIdx.x >> 5;
    int lane = threadIdx.x & 31;
    int n = blockIdx.x * 8 + wid;    // n < N by construction

    const float4* fs4   = (const float4*)fs;
    const float4* fd4   = (const float4*)fd;
    const float4* attn4 = (const float4*)attn;
    const float4* res4  = (const float4*)res;
    float4* out4 = (float4*)out;

    float4 fdv = fd4[(size_t)n * 32 + lane];
    float4 av  = attn4[lane];
    float4 acc = make_float4(0.f, 0.f, 0.f, 0.f);
    float m = -1e30f, s = 0.f;

    int e0 = g_rowptr[n], e1 = g_rowptr[n + 1];
    float4 f0 = make_float4(0.f, 0.f, 0.f, 0.f);
    float4 f1 = f0;
    if (e0 < e1)     f0 = __ldg(&fs4[(size_t)__ldg(&srcidx[e0]) * 32 + lane]);
    if (e0 + 1 < e1) f1 = __ldg(&fs4[(size_t)__ldg(&srcidx[e0 + 1]) * 32 + lane]);

    for (int e = e0; e < e1; e += 2) {
        float4 c0 = f0, c1 = f1;
        bool v1 = (e + 1) < e1;
        if (e + 2 < e1) f0 = __ldg(&fs4[(size_t)__ldg(&srcidx[e + 2]) * 32 + lane]);
        if (e + 3 < e1) f1 = __ldg(&fs4[(size_t)__ldg(&srcidx[e + 3]) * 32 + lane]);

        float ax, ay, az, aw;
        ax = c0.x + fdv.x; ax = (ax > 0.f) ? ax : 0.2f * ax;
        ay = c0.y + fdv.y; ay = (ay > 0.f) ? ay : 0.2f * ay;
        az = c0.z + fdv.z; az = (az > 0.f) ? az : 0.2f * az;
        aw = c0.w + fdv.w; aw = (aw > 0.f) ? aw : 0.2f * aw;
        float t0 = ax * av.x + ay * av.y + az * av.z + aw * av.w;

        ax = c1.x + fdv.x; ax = (ax > 0.f) ? ax : 0.2f * ax;
        ay = c1.y + fdv.y; ay = (ay > 0.f) ? ay : 0.2f * ay;
        az = c1.z + fdv.z; az = (az > 0.f) ? az : 0.2f * az;
        aw = c1.w + fdv.w; aw = (aw > 0.f) ? aw : 0.2f * aw;
        float t1 = ax * av.x + ay * av.y + az * av.z + aw * av.w;

        t0 += __shfl_xor_sync(0xffffffffu, t0, 4);
        t1 += __shfl_xor_sync(0xffffffffu, t1, 4);
        t0 += __shfl_xor_sync(0xffffffffu, t0, 2);
        t1 += __shfl_xor_sync(0xffffffffu, t1, 2);
        t0 += __shfl_xor_sync(0xffffffffu, t0, 1);
        t1 += __shfl_xor_sync(0xffffffffu, t1, 1);

        if (t0 > m) {
            float c = __expf(m - t0);
            acc.x *= c; acc.y *= c; acc.z *= c; acc.w *= c;
            s *= c; m = t0;
        }
        float p0 = __expf(t0 - m);
        s += p0;
        acc.x = fmaf(p0, c0.x, acc.x);
        acc.y = fmaf(p0, c0.y, acc.y);
        acc.z = fmaf(p0, c0.z, acc.z);
        acc.w = fmaf(p0, c0.w, acc.w);

        if (v1) {
            if (t1 > m) {
                float c = __expf(m - t1);
                acc.x *= c; acc.y *= c; acc.z *= c; acc.w *= c;
                s *= c; m = t1;
            }
            float p1 = __expf(t1 - m);
            s += p1;
            acc.x = fmaf(p1, c1.x, acc.x);
            acc.y = fmaf(p1, c1.y, acc.y);
            acc.z = fmaf(p1, c1.z, acc.z);
            acc.w = fmaf(p1, c1.w, acc.w);
        }
    }
    float inv = (e1 > e0) ? (1.f / s) : 0.f;
    float4 r = res4[(size_t)n * 32 + lane];
    float4 o;
    o.x = fmaxf(fmaf(acc.x, inv, r.x), 0.f);
    o.y = fmaxf(fmaf(acc.y, inv, r.y), 0.f);
    o.z = fmaxf(fmaf(acc.z, inv, r.z), 0.f);
    o.w = fmaxf(fmaf(acc.w, inv, r.w), 0.f);
    out4[(size_t)n * 32 + lane] = o;

    // ---- fused BN statistics ----
    int c4 = lane * 4;
    sred[wid][c4 + 0] = o.x;  sred[wid][128 + c4 + 0] = o.x * o.x;
    sred[wid][c4 + 1] = o.y;  sred[wid][128 + c4 + 1] = o.y * o.y;
    sred[wid][c4 + 2] = o.z;  sred[wid][128 + c4 + 2] = o.z * o.z;
    sred[wid][c4 + 3] = o.w;  sred[wid][128 + c4 + 3] = o.w * o.w;
    __syncthreads();
    int t = threadIdx.x;
    if (t < 128) {
        float ss = 0.f, qq = 0.f;
#pragma unroll
        for (int w = 0; w < 8; w++) {
            ss += sred[w][t];
            qq += sred[w][128 + t];
        }
        atomicAdd(&bsum[t], ss);
        atomicAdd(&bsq[t], qq);
    }
}

// ---------------- Layer-2 aggregation (C=47) + head-mean + log_softmax ----------------
__global__ void gat_agg_final(const float* __restrict__ fs, const float* __restrict__ fd,
                              const float* __restrict__ attn, const float* __restrict__ res,
                              float* __restrict__ out, const int* __restrict__ srcidx, int N) {
    int warp = (blockIdx.x * blockDim.x + threadIdx.x) >> 5;
    int lane = threadIdx.x & 31;
    if (warp >= N) return;
    int n = warp;
    int h = lane >> 3, sub = lane & 7;
    int c0i = sub * 6;
    int cnt = (47 - c0i < 6) ? (47 - c0i) : 6;   // 6 or 5
    int base = h * 47 + c0i;

    float fdv[6], av[6], acc[6];
#pragma unroll
    for (int j = 0; j < 6; j++) {
        bool valid = j < cnt;
        fdv[j] = valid ? fd[(size_t)n * 188 + base + j] : 0.f;
        av[j]  = valid ? attn[base + j] : 0.f;
        acc[j] = 0.f;
    }
    float m = -1e30f, s = 0.f;

    int e0 = g_rowptr[n], e1 = g_rowptr[n + 1];
    float f0[6], f1[6];
#pragma unroll
    for (int j = 0; j < 6; j++) { f0[j] = 0.f; f1[j] = 0.f; }
    if (e0 < e1) {
        const float* p = fs + (size_t)__ldg(&srcidx[e0]) * 188 + base;
#pragma unroll
        for (int j = 0; j < 6; j++) if (j < cnt) f0[j] = __ldg(&p[j]);
    }
    if (e0 + 1 < e1) {
        const float* p = fs + (size_t)__ldg(&srcidx[e0 + 1]) * 188 + base;
#pragma unroll
        for (int j = 0; j < 6; j++) if (j < cnt) f1[j] = __ldg(&p[j]);
    }

    for (int e = e0; e < e1; e += 2) {
        float c0[6], c1[6];
#pragma unroll
        for (int j = 0; j < 6; j++) { c0[j] = f0[j]; c1[j] = f1[j]; }
        bool v1 = (e + 1) < e1;
        if (e + 2 < e1) {
            const float* p = fs + (size_t)__ldg(&srcidx[e + 2]) * 188 + base;
#pragma unroll
            for (int j = 0; j < 6; j++) if (j < cnt) f0[j] = __ldg(&p[j]);
        }
        if (e + 3 < e1) {
            const float* p = fs + (size_t)__ldg(&srcidx[e + 3]) * 188 + base;
#pragma unroll
            for (int j = 0; j < 6; j++) if (j < cnt) f1[j] = __ldg(&p[j]);
        }

        float t0 = 0.f, t1 = 0.f;
#pragma unroll
        for (int j = 0; j < 6; j++) {
            float v = c0[j] + fdv[j];
            v = (v > 0.f) ? v : 0.2f * v;
            t0 = fmaf(v, av[j], t0);
        }
#pragma unroll
        for (int j = 0; j < 6; j++) {
            float v = c1[j] + fdv[j];
            v = (v > 0.f) ? v : 0.2f * v;
            t1 = fmaf(v, av[j], t1);
        }
        t0 += __shfl_xor_sync(0xffffffffu, t0, 4);
        t1 += __shfl_xor_sync(0xffffffffu, t1, 4);
        t0 += __shfl_xor_sync(0xffffffffu, t0, 2);
        t1 += __shfl_xor_sync(0xffffffffu, t1, 2);
        t0 += __shfl_xor_sync(0xffffffffu, t0, 1);
        t1 += __shfl_xor_sync(0xffffffffu, t1, 1);

        if (t0 > m) {
            float c = __expf(m - t0);
#pragma unroll
            for (int j = 0; j < 6; j++) acc[j] *= c;
            s *= c; m = t0;
        }
        float p0 = __expf(t0 - m);
        s += p0;
#pragma unroll
        for (int j = 0; j < 6; j++) acc[j] = fmaf(p0, c0[j], acc[j]);

        if (v1) {
            if (t1 > m) {
                float c = __expf(m - t1);
#pragma unroll
                for (int j = 0; j < 6; j++) acc[j] *= c;
                s *= c; m = t1;
            }
            float p1 = __expf(t1 - m);
            s += p1;
#pragma unroll
            for (int j = 0; j < 6; j++) acc[j] = fmaf(p1, c1[j], acc[j]);
        }
    }

    float inv = (e1 > e0) ? (1.f / s) : 0.f;
    float v[6];
#pragma unroll
    for (int j = 0; j < 6; j++) {
        float rr = (j < cnt) ? res[(size_t)n * 188 + base + j] : 0.f;
        v[j] = fmaf(acc[j], inv, rr);
    }
#pragma unroll
    for (int j = 0; j < 6; j++) {
        v[j] += __shfl_xor_sync(0xffffffffu, v[j], 8);
        v[j] += __shfl_xor_sync(0xffffffffu, v[j], 16);
        v[j] *= 0.25f;
    }
    float lm = -1e30f;
#pragma unroll
    for (int j = 0; j < 6; j++) if (j < cnt) lm = fmaxf(lm, v[j]);
    lm = fmaxf(lm, __shfl_xor_sync(0xffffffffu, lm, 4));
    lm = fmaxf(lm, __shfl_xor_sync(0xffffffffu, lm, 2));
    lm = fmaxf(lm, __shfl_xor_sync(0xffffffffu, lm, 1));
    float ls = 0.f;
#pragma unroll
    for (int j = 0; j < 6; j++) if (j < cnt) ls += __expf(v[j] - lm);
    ls += __shfl_xor_sync(0xffffffffu, ls, 4);
    ls += __shfl_xor_sync(0xffffffffu, ls, 2);
    ls += __shfl_xor_sync(0xffffffffu, ls, 1);
    float lse = lm + logf(ls);
    if (h == 0) {
#pragma unroll
        for (int j = 0; j < 6; j++)
            if (j < cnt) out[(size_t)n * 47 + c0i + j] = v[j] - lse;
    }
}

// ---------------- BatchNorm apply: smem-precomputed scale/shift, relu fused ----------------
__global__ void bn_apply(const float4* __restrict__ X, float4* __restrict__ Y,
                         const float* __restrict__ g, const float* __restrict__ b,
                         const float* __restrict__ bsum, const float* __restrict__ bsq, int nrows) {
    __shared__ float ssc[FDIM], ssh[FDIM];
    if (threadIdx.x < FDIM) {
        int c = threadIdx.x;
        float inv_n = 1.0f / (float)nrows;
        float mu  = bsum[c] * inv_n;
        float var = bsq[c] * inv_n - mu * mu;
        float sc  = g[c] * rsqrtf(var + BN_EPS);
        ssc[c] = sc;
        ssh[c] = b[c] - mu * sc;
    }
    __syncthreads();
    int idx = blockIdx.x * blockDim.x + threadIdx.x;   // over nrows*32 float4s
    if (idx >= nrows * 32) return;
    int c4 = (idx & 31) * 4;
    float4 xv = X[idx];
    float4 sc4 = *reinterpret_cast<const float4*>(&ssc[c4]);
    float4 sh4 = *reinterpret_cast<const float4*>(&ssh[c4]);
    float4 o;
    o.x = fmaxf(fmaf(xv.x, sc4.x, sh4.x), 0.f);
    o.y = fmaxf(fmaf(xv.y, sc4.y, sh4.y), 0.f);
    o.z = fmaxf(fmaf(xv.z, sc4.z, sh4.z), 0.f);
    o.w = fmaxf(fmaf(xv.w, sc4.w, sh4.w), 0.f);
    Y[idx] = o;
}

// ---------------- launch ----------------
extern "C" void kernel_launch(void* const* d_in, const int* in_sizes, int n_in,
                              void* d_out, int out_size) {
    const float* x     = (const float*)d_in[0];
    const int*   src   = (const int*)d_in[1];
    const int*   dst   = (const int*)d_in[2];
    const float* Wsrc0 = (const float*)d_in[3];  const float* bsrc0 = (const float*)d_in[4];
    const float* Wdst0 = (const float*)d_in[5];  const float* bdst0 = (const float*)d_in[6];
    const float* attn0 = (const float*)d_in[7];
    const float* Wres0 = (const float*)d_in[8];  const float* bres0 = (const float*)d_in[9];
    const float* Wsrc1 = (const float*)d_in[10]; const float* bsrc1 = (const float*)d_in[11];
    const float* Wdst1 = (const float*)d_in[12]; const float* bdst1 = (const float*)d_in[13];
    const float* attn1 = (const float*)d_in[14];
    const float* Wsrc2 = (const float*)d_in[15]; const float* bsrc2 = (const float*)d_in[16];
    const float* Wdst2 = (const float*)d_in[17]; const float* bdst2 = (const float*)d_in[18];
    const float* attn2 = (const float*)d_in[19];
    const float* Wres2 = (const float*)d_in[20]; const float* bres2 = (const float*)d_in[21];
    const float* g0    = (const float*)d_in[22]; const float* be0   = (const float*)d_in[23];
    const float* g1    = (const float*)d_in[24]; const float* be1   = (const float*)d_in[25];
    float* out = (float*)d_out;

    float *fs, *fd, *res, *hA, *hB, *bs0, *bq0, *bs1, *bq1;
    cudaGetSymbolAddress((void**)&fs,  g_fs);
    cudaGetSymbolAddress((void**)&fd,  g_fd);
    cudaGetSymbolAddress((void**)&res, g_res);
    cudaGetSymbolAddress((void**)&hA,  g_hA);
    cudaGetSymbolAddress((void**)&hB,  g_hB);
    cudaGetSymbolAddress((void**)&bs0, g_bnsum0);
    cudaGetSymbolAddress((void**)&bq0, g_bnsq0);
    cudaGetSymbolAddress((void**)&bs1, g_bnsum1);
    cudaGetSymbolAddress((void**)&bq1, g_bnsq1);

    const int N = NNODES, E = NEDGES;
    dim3 gL0((N + BM - 1) / BM, 2, 3);   // 3 mats, 128 cols
    dim3 gL1((N + BM - 1) / BM, 2, 2);   // 2 mats, 128 cols
    dim3 gL2((N + BM - 1) / BM, 3, 3);   // 3 mats, 188 cols
    int aggGrid = N / 8;                 // exactly 12500 (N % 8 == 0)
    int applyGrid = (N * 32 + 255) / 256;

    build_rowptr<<<(E + 255) / 256, 256>>>(dst, E, N);

    // ---- layer 0: x[N,100] -> 128, Linear residual ----
    gemm3_tf32<<<gL0, 256>>>(x, Wsrc0, Wdst0, Wres0, bsrc0, bdst0, bres0,
                             fs, fd, res, N, 100, 128);
    gat_agg128<<<aggGrid, 256>>>(fs, fd, attn0, res, hA, src, bs0, bq0, N);
    bn_apply<<<applyGrid, 256>>>((const float4*)hA, (float4*)hB, g0, be0, bs0, bq0, N);

    // ---- layer 1: 128 -> 128, Identity residual ----
    gemm3_tf32<<<gL1, 256>>>(hB, Wsrc1, Wdst1, Wdst1, bsrc1, bdst1, bdst1,
                             fs, fd, fd, N, 128, 128);
    gat_agg128<<<aggGrid, 256>>>(fs, fd, attn1, hB, hA, src, bs1, bq1, N);
    bn_apply<<<applyGrid, 256>>>((const float4*)hA, (float4*)hB, g1, be1, bs1, bq1, N);

    // ---- layer 2: 128 -> 188 (H=4, C=47), Linear residual; mean heads + log_softmax ----
    gemm3_tf32<<<gL2, 256>>>(hB, Wsrc2, Wdst2, Wres2, bsrc2, bdst2, bres2,
                             fs, fd, res, N, 128, 188);
    gat_agg_final<<<aggGrid, 256>>>(fs, fd, attn2, res, out, src, N);
}